// round 7
// baseline (speedup 1.0000x reference)
#include <cuda_runtime.h>
#include <cstdint>

// out[n] = S * ( sum_k (x[k]-X_ZP) * y[k,n]  -  Y_ZP * sum_k (x[k]-X_ZP) )
// Exact int32 accumulation. X_SCALE=0.0215, X_ZP=-25, Y_SCALE=0.0176, Y_ZP=18
//
// Single fused kernel, grid (16 n-tiles x 64 K-splits) x 256 thr.
// Streaming phase identical to the 75.7us/6.8TB/s R5 gemv (untouched).
// Per-tile tickets: the last FOUR blocks to finish a tile become reducers
// (64 reducer blocks chip-wide), each handling 256 columns x 64 splits.
// Early tiles' reducers overlap with laggard tiles' streaming (single-wave
// residency + CTA spread), hiding the tail. Counters self-reset for graph
// replay.

#define KDIM 8192
#define NDIM 16384
#define THREADS 256
#define COLS_PER_THREAD 4
#define COLS_PER_BLOCK (THREADS * COLS_PER_THREAD)    // 1024
#define N_TILES (NDIM / COLS_PER_BLOCK)               // 16
#define KCHUNK 128
#define SPLITS (KDIM / KCHUNK)                        // 64
#define REDUCERS_PER_TILE 4
#define COLS_PER_REDUCER (COLS_PER_BLOCK / REDUCERS_PER_TILE)  // 256

__device__ int g_part[SPLITS][NDIM];            // per-split partials
__device__ volatile unsigned g_tick[N_TILES];   // streaming-done tickets
__device__ unsigned g_fin[N_TILES];             // reducer-done tickets

__global__ __launch_bounds__(THREADS, 8) void gemv_fused_kernel(
    const int* __restrict__ x, const int* __restrict__ y,
    float* __restrict__ out)
{
    __shared__ int sa[KCHUNK];
    __shared__ unsigned s_ticket;
    __shared__ int s_warp[THREADS / 32];

    const int tid   = threadIdx.x;
    const int tile  = blockIdx.x;
    const int split = blockIdx.y;
    const int k0    = split * KCHUNK;

    // a[k] = x[k] - X_ZP = x[k] + 25
    if (tid < KCHUNK)
        sa[tid] = x[k0 + tid] + 25;
    __syncthreads();

    const int n0 = tile * COLS_PER_BLOCK + tid * COLS_PER_THREAD;
    const int4* yp = reinterpret_cast<const int4*>(y + (size_t)k0 * NDIM + n0);
    const size_t strideV = NDIM / 4;

    int a0 = 0, a1 = 0, a2 = 0, a3 = 0;
    #pragma unroll 8
    for (int kk = 0; kk < KCHUNK; kk++) {
        const int a = sa[kk];
        const int4 v = __ldcs(&yp[(size_t)kk * strideV]);
        a0 += a * v.x;  a1 += a * v.y;  a2 += a * v.z;  a3 += a * v.w;
    }

    *reinterpret_cast<int4*>(&g_part[split][n0]) = make_int4(a0, a1, a2, a3);

    // Publish partials, take a per-tile ticket.
    __threadfence();
    __syncthreads();
    if (tid == 0)
        s_ticket = atomicAdd((unsigned*)&g_tick[tile], 1u);
    __syncthreads();
    const unsigned ticket = s_ticket;
    if (ticket < SPLITS - REDUCERS_PER_TILE) return;

    // ---- Reducer path (last 4 blocks of this tile) ----
    const int quarter = (int)ticket - (SPLITS - REDUCERS_PER_TILE);  // 0..3

    // Zero-point correction (independent of partials; overlaps the spin):
    // sum_a = sum_k (x[k] + 25)
    int sx = 0;
    #pragma unroll
    for (int i = 0; i < KDIM / THREADS; i++)
        sx += __ldg(&x[tid + i * THREADS]);
    #pragma unroll
    for (int o = 16; o > 0; o >>= 1)
        sx += __shfl_down_sync(0xffffffffu, sx, o);
    if ((tid & 31) == 0) s_warp[tid >> 5] = sx;
    __syncthreads();
    int sum_a = 25 * KDIM;
    #pragma unroll
    for (int w = 0; w < THREADS / 32; w++) sum_a += s_warp[w];

    // Wait for all 64 splits of this tile.
    if (tid == 0) {
        while (g_tick[tile] < SPLITS) __nanosleep(64);
    }
    __syncthreads();
    __threadfence();   // acquire partials

    // Reduce: one column per thread, 64 splits, 4 independent chains.
    const int col = tile * COLS_PER_BLOCK + quarter * COLS_PER_REDUCER + tid;
    int r0 = 0, r1 = 0, r2 = 0, r3 = 0;
    #pragma unroll
    for (int s = 0; s < SPLITS; s += 4) {
        r0 += g_part[s + 0][col];
        r1 += g_part[s + 1][col];
        r2 += g_part[s + 2][col];
        r3 += g_part[s + 3][col];
    }
    const int acc = (r0 + r1) + (r2 + r3);

    const float S = (float)(0.0215 * 0.0176);
    out[col] = S * (float)(acc - 18 * sum_a);

    // Self-reset for the next graph replay: last reducer of the tile.
    __syncthreads();
    if (tid == 0) {
        unsigned f = atomicAdd(&g_fin[tile], 1u);
        if (f == REDUCERS_PER_TILE - 1) {
            g_fin[tile] = 0;
            g_tick[tile] = 0;
            __threadfence();
        }
    }
}

extern "C" void kernel_launch(void* const* d_in, const int* in_sizes, int n_in,
                              void* d_out, int out_size) {
    const int* x = (const int*)d_in[0];   // [K]
    const int* y = (const int*)d_in[1];   // [K, N]
    float* out = (float*)d_out;           // [N]

    dim3 grid(N_TILES, SPLITS);
    gemv_fused_kernel<<<grid, THREADS>>>(x, y, out);
}

// round 8
// speedup vs baseline: 1.0151x; 1.0151x over previous
#include <cuda_runtime.h>
#include <cstdint>

// out[n] = S * ( sum_k (x[k]-X_ZP) * y[k,n]  -  Y_ZP * sum_k (x[k]-X_ZP) )
// Exact int32 accumulation. X_SCALE=0.0215, X_ZP=-25, Y_SCALE=0.0176, Y_ZP=18
//
// gemv:     (16 n-tiles x 64 K-splits) x 256 thr, coalesced int4 __ldcs
//           stream at ~6.8 TB/s (84.5% of HBM spec — roofline, untouched).
// finalize: 128 blocks x 256 thr. 8 threads per int4 column-group, each
//           loading 8 independent int4 partials into held registers
//           (MLP=8, 128 B in flight/thread), smem combine. No atomics.

#define KDIM 8192
#define NDIM 16384
#define THREADS 256
#define COLS_PER_THREAD 4
#define COLS_PER_BLOCK (THREADS * COLS_PER_THREAD)    // 1024
#define N_TILES (NDIM / COLS_PER_BLOCK)               // 16
#define KCHUNK 128
#define SPLITS (KDIM / KCHUNK)                        // 64

#define FIN_THREADS 256
#define FIN_SEGS 8                                    // threads per col-group
#define FIN_GRPS 32                                   // int4 groups per block
#define FIN_SPL_PER_SEG (SPLITS / FIN_SEGS)           // 8
#define FIN_COLS (FIN_GRPS * 4)                       // 128 cols per block
#define FIN_BLOCKS (NDIM / FIN_COLS)                  // 128

__device__ int g_part[SPLITS][NDIM];   // per-split partial dot products
__device__ int g_sa_part[SPLITS];      // per-split sum of (x[k]+25)

__global__ __launch_bounds__(THREADS) void gemv_kernel(
    const int* __restrict__ x, const int* __restrict__ y)
{
    __shared__ int sa[KCHUNK];
    const int tid   = threadIdx.x;
    const int split = blockIdx.y;
    const int k0    = split * KCHUNK;

    // a[k] = x[k] - X_ZP = x[k] + 25
    if (tid < KCHUNK)
        sa[tid] = x[k0 + tid] + 25;
    __syncthreads();

    const int n0 = blockIdx.x * COLS_PER_BLOCK + tid * COLS_PER_THREAD;
    const int4* yp = reinterpret_cast<const int4*>(y + (size_t)k0 * NDIM + n0);
    const size_t strideV = NDIM / 4;

    int a0 = 0, a1 = 0, a2 = 0, a3 = 0;
    #pragma unroll 8
    for (int kk = 0; kk < KCHUNK; kk++) {
        const int a = sa[kk];
        const int4 v = __ldcs(&yp[(size_t)kk * strideV]);
        a0 += a * v.x;  a1 += a * v.y;  a2 += a * v.z;  a3 += a * v.w;
    }

    *reinterpret_cast<int4*>(&g_part[split][n0]) = make_int4(a0, a1, a2, a3);

    // one n-tile per split contributes the sum-of-a partial
    if (blockIdx.x == 0 && tid < 32) {
        int s = 0;
        #pragma unroll
        for (int i = 0; i < KCHUNK / 32; i++)
            s += sa[tid + i * 32];
        #pragma unroll
        for (int o = 16; o > 0; o >>= 1)
            s += __shfl_down_sync(0xffffffffu, s, o);
        if (tid == 0) g_sa_part[split] = s;
    }
}

__global__ __launch_bounds__(FIN_THREADS) void finalize_kernel(float* __restrict__ out) {
    __shared__ int4 s_red[FIN_SEGS][FIN_GRPS];
    __shared__ int s_sa;

    const int tid = threadIdx.x;
    const int seg = tid >> 5;           // 0..7 : which 8-split segment
    const int grp = tid & 31;           // 0..31: int4 column-group in block
    const int g4  = blockIdx.x * FIN_GRPS + grp;

    if (tid < 32) {
        int s = g_sa_part[tid] + g_sa_part[tid + 32];
        #pragma unroll
        for (int o = 16; o > 0; o >>= 1)
            s += __shfl_down_sync(0xffffffffu, s, o);
        if (tid == 0) s_sa = s;
    }

    // 8 fully independent int4 loads, held in registers (MLP = 8).
    int4 v[FIN_SPL_PER_SEG];
    #pragma unroll
    for (int i = 0; i < FIN_SPL_PER_SEG; i++)
        v[i] = __ldcs(reinterpret_cast<const int4*>(
                          g_part[seg * FIN_SPL_PER_SEG + i]) + g4);

    int4 acc;
    acc.x = ((v[0].x + v[1].x) + (v[2].x + v[3].x)) +
            ((v[4].x + v[5].x) + (v[6].x + v[7].x));
    acc.y = ((v[0].y + v[1].y) + (v[2].y + v[3].y)) +
            ((v[4].y + v[5].y) + (v[6].y + v[7].y));
    acc.z = ((v[0].z + v[1].z) + (v[2].z + v[3].z)) +
            ((v[4].z + v[5].z) + (v[6].z + v[7].z));
    acc.w = ((v[0].w + v[1].w) + (v[2].w + v[3].w)) +
            ((v[4].w + v[5].w) + (v[6].w + v[7].w));
    s_red[seg][grp] = acc;
    __syncthreads();

    if (tid < FIN_COLS) {
        const int grp2 = tid >> 2;
        const int comp = tid & 3;
        int a = 0;
        #pragma unroll
        for (int s = 0; s < FIN_SEGS; s++)
            a += reinterpret_cast<const int*>(&s_red[s][grp2])[comp];

        const float S = (float)(0.0215 * 0.0176);
        out[blockIdx.x * FIN_COLS + tid] = S * (float)(a - 18 * s_sa);
    }
}

extern "C" void kernel_launch(void* const* d_in, const int* in_sizes, int n_in,
                              void* d_out, int out_size) {
    const int* x = (const int*)d_in[0];   // [K]
    const int* y = (const int*)d_in[1];   // [K, N]
    float* out = (float*)d_out;           // [N]

    dim3 grid(N_TILES, SPLITS);
    gemv_kernel<<<grid, THREADS>>>(x, y);
    finalize_kernel<<<FIN_BLOCKS, FIN_THREADS>>>(out);
}

// round 9
// speedup vs baseline: 1.0186x; 1.0035x over previous
#include <cuda_runtime.h>
#include <cstdint>

// out[n] = S * ( sum_k (x[k]-X_ZP) * y[k,n]  -  Y_ZP * sum_k (x[k]-X_ZP) )
// Exact int32 accumulation. X_SCALE=0.0215, X_ZP=-25, Y_SCALE=0.0176, Y_ZP=18
//
// gemv:     (16 n-tiles x 64 K-splits) x 256 thr, coalesced int4 __ldcs
//           stream. Partials accumulated with atomicAdd (REDG) directly into
//           a 64 KB L2-resident accumulator — no 4 MB partial array, no
//           zero kernel.
// finalize: 64 blocks x 256 thr. Reads the 64 KB accumulator (L2 hot),
//           writes fp32 output, and RESETS the accumulator to zero so every
//           graph replay starts clean (thread owns its column: race-free).

#define KDIM 8192
#define NDIM 16384
#define THREADS 256
#define COLS_PER_THREAD 4
#define COLS_PER_BLOCK (THREADS * COLS_PER_THREAD)    // 1024
#define N_TILES (NDIM / COLS_PER_BLOCK)               // 16
#define KCHUNK 128
#define SPLITS (KDIM / KCHUNK)                        // 64

__device__ int g_acc[NDIM];            // zero at load; finalize re-zeros
__device__ int g_sa_part[SPLITS];      // plain stores, overwritten each run

__global__ __launch_bounds__(THREADS) void gemv_kernel(
    const int* __restrict__ x, const int* __restrict__ y)
{
    __shared__ int sa[KCHUNK];
    const int tid   = threadIdx.x;
    const int split = blockIdx.y;
    const int k0    = split * KCHUNK;

    // a[k] = x[k] - X_ZP = x[k] + 25
    if (tid < KCHUNK)
        sa[tid] = x[k0 + tid] + 25;
    __syncthreads();

    const int n0 = blockIdx.x * COLS_PER_BLOCK + tid * COLS_PER_THREAD;
    const int4* yp = reinterpret_cast<const int4*>(y + (size_t)k0 * NDIM + n0);
    const size_t strideV = NDIM / 4;

    int a0 = 0, a1 = 0, a2 = 0, a3 = 0;
    #pragma unroll 8
    for (int kk = 0; kk < KCHUNK; kk++) {
        const int a = sa[kk];
        const int4 v = __ldcs(&yp[(size_t)kk * strideV]);
        a0 += a * v.x;  a1 += a * v.y;  a2 += a * v.z;  a3 += a * v.w;
    }

    // No-return atomics -> REDG into L2-resident accumulator.
    atomicAdd(&g_acc[n0 + 0], a0);
    atomicAdd(&g_acc[n0 + 1], a1);
    atomicAdd(&g_acc[n0 + 2], a2);
    atomicAdd(&g_acc[n0 + 3], a3);

    // one n-tile per split contributes the sum-of-a partial (plain store)
    if (blockIdx.x == 0 && tid < 32) {
        int s = 0;
        #pragma unroll
        for (int i = 0; i < KCHUNK / 32; i++)
            s += sa[tid + i * 32];
        #pragma unroll
        for (int o = 16; o > 0; o >>= 1)
            s += __shfl_down_sync(0xffffffffu, s, o);
        if (tid == 0) g_sa_part[split] = s;
    }
}

__global__ __launch_bounds__(THREADS) void finalize_kernel(float* __restrict__ out) {
    __shared__ int s_sa;
    const int tid = threadIdx.x;

    if (tid < 32) {
        int s = g_sa_part[tid] + g_sa_part[tid + 32];
        #pragma unroll
        for (int o = 16; o > 0; o >>= 1)
            s += __shfl_down_sync(0xffffffffu, s, o);
        if (tid == 0) s_sa = s;
    }
    __syncthreads();

    const int n = blockIdx.x * THREADS + tid;
    const int acc = g_acc[n];
    g_acc[n] = 0;                       // reset for next graph replay

    const float S = (float)(0.0215 * 0.0176);
    out[n] = S * (float)(acc - 18 * s_sa);
}

extern "C" void kernel_launch(void* const* d_in, const int* in_sizes, int n_in,
                              void* d_out, int out_size) {
    const int* x = (const int*)d_in[0];   // [K]
    const int* y = (const int*)d_in[1];   // [K, N]
    float* out = (float*)d_out;           // [N]

    dim3 grid(N_TILES, SPLITS);
    gemv_kernel<<<grid, THREADS>>>(x, y);
    finalize_kernel<<<NDIM / THREADS, THREADS>>>(out);
}